// round 6
// baseline (speedup 1.0000x reference)
#include <cuda_runtime.h>
#include <math.h>

#define NN 50000
#define NE 800000
#define FD 128
#define NC 40

typedef unsigned long long u64;

// Scratch (device globals: allocation-free per harness rules)
__device__ __align__(16) float g_agg[(size_t)NN * FD];  // layer1 [NN,128]; reused as [NN,40] in layer2
__device__ __align__(16) float g_h[(size_t)NN * FD];
__device__ __align__(16) float g_p[(size_t)NN * NC];    // h @ W2_l
__device__ __align__(16) float g_r[(size_t)NN * NC];    // h @ W2_r + b2
__device__ float g_deg[NN];

// ---- packed f32x2 helpers (Blackwell dual-fp32 pipe) ----
__device__ __forceinline__ u64 pk2(float lo, float hi) {
    u64 r; asm("mov.b64 %0, {%1, %2};" : "=l"(r) : "f"(lo), "f"(hi)); return r;
}
__device__ __forceinline__ u64 fma2(u64 a, u64 b, u64 c) {
    u64 d; asm("fma.rn.f32x2 %0, %1, %2, %3;" : "=l"(d) : "l"(a), "l"(b), "l"(c)); return d;
}
__device__ __forceinline__ void unpk(u64 v, float& lo, float& hi) {
    asm("mov.b64 {%0, %1}, %2;" : "=f"(lo), "=f"(hi) : "l"(v));
}
__device__ __forceinline__ void red4(float* p, float4 v) {
    asm volatile("red.global.add.v4.f32 [%0], {%1,%2,%3,%4};"
                 :: "l"(p), "f"(v.x), "f"(v.y), "f"(v.z), "f"(v.w) : "memory");
}
__device__ __forceinline__ void red1(float* p, float v) {
    asm volatile("red.global.add.f32 [%0], %1;" :: "l"(p), "f"(v) : "memory");
}

// ---- zero kernels ----
__global__ void zero1_kernel() {
    int i = blockIdx.x * blockDim.x + threadIdx.x;
    if (i < NN * FD / 4)
        reinterpret_cast<float4*>(g_agg)[i] = make_float4(0.f, 0.f, 0.f, 0.f);
    if (i < NN) g_deg[i] = 0.f;
}
__global__ void zero2_kernel() {
    int i = blockIdx.x * blockDim.x + threadIdx.x;
    if (i < NN * NC / 4)
        reinterpret_cast<float4*>(g_agg)[i] = make_float4(0.f, 0.f, 0.f, 0.f);
}

// ---- layer-1 scatter: one warp per edge, 128-dim float4 gather + v4 reduce ----
__global__ void scatter1_kernel(const float* __restrict__ x,
                                const int* __restrict__ ei) {
    int lane = threadIdx.x & 31;
    int e = blockIdx.x * 8 + (threadIdx.x >> 5);
    if (e >= NE) return;
    int src = __ldg(ei + e);
    int dst = __ldg(ei + NE + e);
    float4 v = __ldg(reinterpret_cast<const float4*>(x) + (size_t)src * 32 + lane);
    red4(g_agg + (size_t)dst * FD + lane * 4, v);
    if (lane == 0) red1(g_deg + dst, 1.f);
}

// ---- layer-2 scatter: 40-dim, one warp per 3 edges (10 lanes each) ----
__global__ void scatter2_kernel(const int* __restrict__ ei) {
    int lane = threadIdx.x & 31;
    int w = blockIdx.x * 8 + (threadIdx.x >> 5);
    if (lane >= 30) return;
    int g = (lane >= 20) ? 2 : ((lane >= 10) ? 1 : 0);
    int c = lane - 10 * g;
    int e = 3 * w + g;
    if (e >= NE) return;
    int src = __ldg(ei + e);
    int dst = __ldg(ei + NE + e);
    float4 v = __ldg(reinterpret_cast<const float4*>(g_p) + (size_t)src * 10 + c);
    red4(g_agg + (size_t)dst * NC + c * 4, v);
}

// ---- layer 1 GEMM: h = relu( (agg/deg)@W1_l + x@W1_r + b1 ) ----
// 32 nodes/block; SMEM holds duplicated activations k-major so dup(a) is a
// direct 128-bit LDS; weights load as natural f32x2 column pairs (no movs).
// Thread = 2 nodes x 8 cols; 16 fma2 + 4 LDG.128 + 2 LDS.128 per k.
__global__ __launch_bounds__(256, 2) void sage1_kernel(
    const float* __restrict__ x,
    const float* __restrict__ Wl,
    const float* __restrict__ Wr,
    const float* __restrict__ b) {
    extern __shared__ float sm[];
    float* sa = sm;             // [128][72]: dup pairs (a,a) per node
    float* sx = sm + 128 * 72;  // [128][72]
    __shared__ float sinv[32];

    int tid = threadIdx.x;
    int nb = blockIdx.x * 32;

    if (tid < 32) {
        int nd = nb + tid;
        float d = (nd < NN) ? g_deg[nd] : 1.f;
        sinv[tid] = 1.f / fmaxf(d, 1.f);
    }
    __syncthreads();
    for (int idx = tid; idx < 32 * FD; idx += 256) {
        int n = idx >> 7, k = idx & 127, nd = nb + n;
        float a = 0.f, xv = 0.f;
        if (nd < NN) {
            a = g_agg[(size_t)nd * FD + k] * sinv[n];
            xv = x[(size_t)nd * FD + k];
        }
        *reinterpret_cast<float2*>(sa + k * 72 + 2 * n) = make_float2(a, a);
        *reinterpret_cast<float2*>(sx + k * 72 + 2 * n) = make_float2(xv, xv);
    }
    __syncthreads();

    int tx = tid & 15, tyn = tid >> 4;
    int c0 = tx * 8;

    u64 acc[2][4];
    {
        ulonglong2 b01 = *reinterpret_cast<const ulonglong2*>(b + c0);
        ulonglong2 b23 = *reinterpret_cast<const ulonglong2*>(b + c0 + 4);
        acc[0][0] = acc[1][0] = b01.x;
        acc[0][1] = acc[1][1] = b01.y;
        acc[0][2] = acc[1][2] = b23.x;
        acc[0][3] = acc[1][3] = b23.y;
    }

#pragma unroll 4
    for (int k = 0; k < FD; ++k) {
        ulonglong2 wl0 = *reinterpret_cast<const ulonglong2*>(Wl + (size_t)k * FD + c0);
        ulonglong2 wl1 = *reinterpret_cast<const ulonglong2*>(Wl + (size_t)k * FD + c0 + 4);
        ulonglong2 wr0 = *reinterpret_cast<const ulonglong2*>(Wr + (size_t)k * FD + c0);
        ulonglong2 wr1 = *reinterpret_cast<const ulonglong2*>(Wr + (size_t)k * FD + c0 + 4);
        ulonglong2 ad = *reinterpret_cast<const ulonglong2*>(sa + k * 72 + 4 * tyn);
        ulonglong2 xd = *reinterpret_cast<const ulonglong2*>(sx + k * 72 + 4 * tyn);

        acc[0][0] = fma2(ad.x, wl0.x, acc[0][0]);
        acc[0][1] = fma2(ad.x, wl0.y, acc[0][1]);
        acc[0][2] = fma2(ad.x, wl1.x, acc[0][2]);
        acc[0][3] = fma2(ad.x, wl1.y, acc[0][3]);
        acc[1][0] = fma2(ad.y, wl0.x, acc[1][0]);
        acc[1][1] = fma2(ad.y, wl0.y, acc[1][1]);
        acc[1][2] = fma2(ad.y, wl1.x, acc[1][2]);
        acc[1][3] = fma2(ad.y, wl1.y, acc[1][3]);
        acc[0][0] = fma2(xd.x, wr0.x, acc[0][0]);
        acc[0][1] = fma2(xd.x, wr0.y, acc[0][1]);
        acc[0][2] = fma2(xd.x, wr1.x, acc[0][2]);
        acc[0][3] = fma2(xd.x, wr1.y, acc[0][3]);
        acc[1][0] = fma2(xd.y, wr0.x, acc[1][0]);
        acc[1][1] = fma2(xd.y, wr0.y, acc[1][1]);
        acc[1][2] = fma2(xd.y, wr1.x, acc[1][2]);
        acc[1][3] = fma2(xd.y, wr1.y, acc[1][3]);
    }

#pragma unroll
    for (int n = 0; n < 2; ++n) {
        int nd = nb + 2 * tyn + n;
        if (nd >= NN) continue;
        float q[8];
        unpk(acc[n][0], q[0], q[1]);
        unpk(acc[n][1], q[2], q[3]);
        unpk(acc[n][2], q[4], q[5]);
        unpk(acc[n][3], q[6], q[7]);
        float4 v0 = make_float4(fmaxf(q[0], 0.f), fmaxf(q[1], 0.f),
                                fmaxf(q[2], 0.f), fmaxf(q[3], 0.f));
        float4 v1 = make_float4(fmaxf(q[4], 0.f), fmaxf(q[5], 0.f),
                                fmaxf(q[6], 0.f), fmaxf(q[7], 0.f));
        *reinterpret_cast<float4*>(g_h + (size_t)nd * FD + c0) = v0;
        *reinterpret_cast<float4*>(g_h + (size_t)nd * FD + c0 + 4) = v1;
    }
}

// ---- layer-2 projection: p = h@W2_l, r = h@W2_r + b2  (both [N,40]) ----
// 64 nodes/block; nodes packed in f32x2 (k-major SMEM pair load), weight
// scalars duplicated. Thread = 8 nodes x 2 cols x 2 mats = 16 fma2/k.
__global__ __launch_bounds__(256, 2) void proj2_kernel(
    const float* __restrict__ Wl,
    const float* __restrict__ Wr,
    const float* __restrict__ b2) {
    __shared__ float sh[128 * 68];
    int tid = threadIdx.x;
    int nb = blockIdx.x * 64;

    for (int idx = tid; idx < 64 * FD; idx += 256) {
        int n = idx >> 7, k = idx & 127, nd = nb + n;
        sh[k * 68 + n] = (nd < NN) ? g_h[(size_t)nd * FD + k] : 0.f;
    }
    __syncthreads();

    int ty = tid >> 5, tx = tid & 31;
    bool act = tx < 20;
    int cx = act ? tx : 19;
    int c0 = 2 * cx;
    int nl = ty * 8;

    u64 accP[4][2], accR[4][2];
    {
        float b0 = __ldg(b2 + c0), b1v = __ldg(b2 + c0 + 1);
        u64 z = pk2(0.f, 0.f), bb0 = pk2(b0, b0), bb1 = pk2(b1v, b1v);
#pragma unroll
        for (int p = 0; p < 4; ++p) {
            accP[p][0] = z; accP[p][1] = z;
            accR[p][0] = bb0; accR[p][1] = bb1;
        }
    }

#pragma unroll 4
    for (int k = 0; k < FD; ++k) {
        float2 wl = *reinterpret_cast<const float2*>(Wl + (size_t)k * NC + c0);
        float2 wr = *reinterpret_cast<const float2*>(Wr + (size_t)k * NC + c0);
        u64 wl0 = pk2(wl.x, wl.x), wl1 = pk2(wl.y, wl.y);
        u64 wr0 = pk2(wr.x, wr.x), wr1 = pk2(wr.y, wr.y);
        ulonglong2 h01 = *reinterpret_cast<const ulonglong2*>(sh + k * 68 + nl);
        ulonglong2 h23 = *reinterpret_cast<const ulonglong2*>(sh + k * 68 + nl + 4);

        accP[0][0] = fma2(h01.x, wl0, accP[0][0]);
        accP[0][1] = fma2(h01.x, wl1, accP[0][1]);
        accP[1][0] = fma2(h01.y, wl0, accP[1][0]);
        accP[1][1] = fma2(h01.y, wl1, accP[1][1]);
        accP[2][0] = fma2(h23.x, wl0, accP[2][0]);
        accP[2][1] = fma2(h23.x, wl1, accP[2][1]);
        accP[3][0] = fma2(h23.y, wl0, accP[3][0]);
        accP[3][1] = fma2(h23.y, wl1, accP[3][1]);
        accR[0][0] = fma2(h01.x, wr0, accR[0][0]);
        accR[0][1] = fma2(h01.x, wr1, accR[0][1]);
        accR[1][0] = fma2(h01.y, wr0, accR[1][0]);
        accR[1][1] = fma2(h01.y, wr1, accR[1][1]);
        accR[2][0] = fma2(h23.x, wr0, accR[2][0]);
        accR[2][1] = fma2(h23.x, wr1, accR[2][1]);
        accR[3][0] = fma2(h23.y, wr0, accR[3][0]);
        accR[3][1] = fma2(h23.y, wr1, accR[3][1]);
    }

    if (act) {
#pragma unroll
        for (int p = 0; p < 4; ++p) {
            int n0 = nb + nl + 2 * p;
            float pa0, pa1, pb0, pb1, ra0, ra1, rb0, rb1;
            unpk(accP[p][0], pa0, pa1);
            unpk(accP[p][1], pb0, pb1);
            unpk(accR[p][0], ra0, ra1);
            unpk(accR[p][1], rb0, rb1);
            if (n0 < NN) {
                *reinterpret_cast<float2*>(g_p + (size_t)n0 * NC + c0) = make_float2(pa0, pb0);
                *reinterpret_cast<float2*>(g_r + (size_t)n0 * NC + c0) = make_float2(ra0, rb0);
            }
            if (n0 + 1 < NN) {
                *reinterpret_cast<float2*>(g_p + (size_t)(n0 + 1) * NC + c0) = make_float2(pa1, pb1);
                *reinterpret_cast<float2*>(g_r + (size_t)(n0 + 1) * NC + c0) = make_float2(ra1, rb1);
            }
        }
    }
}

// ---- final: out = log_softmax(relu(agg2/deg + r)) , one warp per node ----
__global__ void final_kernel(float* __restrict__ out) {
    int lane = threadIdx.x & 31;
    int node = blockIdx.x * 8 + (threadIdx.x >> 5);  // grid covers NN exactly
    bool act = lane < 20;
    int cx = act ? lane : 19;

    float inv = 1.f / fmaxf(g_deg[node], 1.f);
    float2 a = *reinterpret_cast<const float2*>(g_agg + (size_t)node * NC + 2 * cx);
    float2 r = *reinterpret_cast<const float2*>(g_r + (size_t)node * NC + 2 * cx);
    float za = fmaxf(fmaf(a.x, inv, r.x), 0.f);
    float zb = fmaxf(fmaf(a.y, inv, r.y), 0.f);

    float m = act ? fmaxf(za, zb) : -3.0e38f;
#pragma unroll
    for (int o = 16; o > 0; o >>= 1)
        m = fmaxf(m, __shfl_xor_sync(0xffffffffu, m, o));
    float s = act ? (expf(za - m) + expf(zb - m)) : 0.f;
#pragma unroll
    for (int o = 16; o > 0; o >>= 1)
        s += __shfl_xor_sync(0xffffffffu, s, o);
    float lse = m + logf(s);

    if (act)
        *reinterpret_cast<float2*>(out + (size_t)node * NC + 2 * lane) =
            make_float2(za - lse, zb - lse);
}

extern "C" void kernel_launch(void* const* d_in, const int* in_sizes, int n_in,
                              void* d_out, int out_size) {
    const float* x   = (const float*)d_in[0];
    const int*   ei  = (const int*)d_in[1];
    const float* W1l = (const float*)d_in[2];
    const float* W1r = (const float*)d_in[3];
    const float* b1  = (const float*)d_in[4];
    const float* W2l = (const float*)d_in[5];
    const float* W2r = (const float*)d_in[6];
    const float* b2  = (const float*)d_in[7];
    float* out = (float*)d_out;

    static const int SAGE1_SMEM = 2 * 128 * 72 * 4;  // 73728 B dynamic
    cudaFuncSetAttribute(sage1_kernel, cudaFuncAttributeMaxDynamicSharedMemorySize,
                         SAGE1_SMEM);

    zero1_kernel<<<6250, 256>>>();                       // 1.6M f4 + deg
    scatter1_kernel<<<100000, 256>>>(x, ei);             // 1 warp/edge
    sage1_kernel<<<1563, 256, SAGE1_SMEM>>>(x, W1l, W1r, b1);
    zero2_kernel<<<1954, 256>>>();                       // 500k f4
    proj2_kernel<<<782, 256>>>(W2l, W2r, b2);            // 64 nodes/block
    scatter2_kernel<<<33334, 256>>>(ei);                 // 1 warp / 3 edges
    final_kernel<<<6250, 256>>>(out);                    // 8 nodes/block
}

// round 7
// speedup vs baseline: 1.3471x; 1.3471x over previous
#include <cuda_runtime.h>
#include <math.h>

#define NN 50000
#define NE 800000
#define FD 128
#define NC 40

typedef unsigned long long u64;

// Scratch (device globals: allocation-free per harness rules)
__device__ __align__(16) float g_agg[(size_t)NN * FD];  // layer1 [NN,128]; reused [NN,40] layer2
__device__ __align__(16) float g_h[(size_t)NN * FD];
__device__ __align__(16) float g_p[(size_t)NN * NC];    // h @ W2_l
__device__ __align__(16) float g_r[(size_t)NN * NC];    // h @ W2_r + b2
__device__ float g_deg[NN];

// ---- packed f32x2 helpers (Blackwell dual-fp32 pipe) ----
__device__ __forceinline__ u64 pk2(float lo, float hi) {
    u64 r; asm("mov.b64 %0, {%1, %2};" : "=l"(r) : "f"(lo), "f"(hi)); return r;
}
__device__ __forceinline__ u64 fma2(u64 a, u64 b, u64 c) {
    u64 d; asm("fma.rn.f32x2 %0, %1, %2, %3;" : "=l"(d) : "l"(a), "l"(b), "l"(c)); return d;
}
__device__ __forceinline__ void unpk(u64 v, float& lo, float& hi) {
    asm("mov.b64 {%0, %1}, %2;" : "=f"(lo), "=f"(hi) : "l"(v));
}
__device__ __forceinline__ void red4(float* p, float4 v) {
    asm volatile("red.global.add.v4.f32 [%0], {%1,%2,%3,%4};"
                 :: "l"(p), "f"(v.x), "f"(v.y), "f"(v.z), "f"(v.w) : "memory");
}
__device__ __forceinline__ void red1(float* p, float v) {
    asm volatile("red.global.add.f32 [%0], %1;" :: "l"(p), "f"(v) : "memory");
}

// ---- zero kernels ----
__global__ void zero1_kernel() {
    int i = blockIdx.x * blockDim.x + threadIdx.x;
    if (i < NN * FD / 4)
        reinterpret_cast<float4*>(g_agg)[i] = make_float4(0.f, 0.f, 0.f, 0.f);
    if (i < NN) g_deg[i] = 0.f;
}
__global__ void zero2_kernel() {
    int i = blockIdx.x * blockDim.x + threadIdx.x;
    if (i < NN * NC / 4)
        reinterpret_cast<float4*>(g_agg)[i] = make_float4(0.f, 0.f, 0.f, 0.f);
}

// ---- layer-1 scatter: R2-proven grid-stride, one warp per edge ----
__global__ void scatter1_kernel(const float* __restrict__ x,
                                const int* __restrict__ ei) {
    int lane = threadIdx.x & 31;
    int wid = (blockIdx.x * blockDim.x + threadIdx.x) >> 5;
    int nw = (gridDim.x * blockDim.x) >> 5;
    for (int e = wid; e < NE; e += nw) {
        int src = __ldg(ei + e);
        int dst = __ldg(ei + NE + e);
        float4 v = __ldg(reinterpret_cast<const float4*>(x) + (size_t)src * 32 + lane);
        red4(g_agg + (size_t)dst * FD + lane * 4, v);
        if (lane == 0) red1(g_deg + dst, 1.0f);
    }
}

// ---- layer-2 scatter: 40-dim projected features, grid-stride, 3 edges/warp ----
__global__ void scatter2_kernel(const int* __restrict__ ei) {
    int lane = threadIdx.x & 31;
    int wid = (blockIdx.x * blockDim.x + threadIdx.x) >> 5;
    int nw = (gridDim.x * blockDim.x) >> 5;
    if (lane >= 30) return;
    int g = (lane >= 20) ? 2 : ((lane >= 10) ? 1 : 0);
    int c = lane - 10 * g;
    for (int w = wid; w * 3 + g < NE; w += nw) {
        int e = 3 * w + g;
        int src = __ldg(ei + e);
        int dst = __ldg(ei + NE + e);
        float4 v = __ldg(reinterpret_cast<const float4*>(g_p) + (size_t)src * 10 + c);
        red4(g_agg + (size_t)dst * NC + c * 4, v);
    }
}

// ---- layer 1 GEMM (R2-proven): h = relu( (agg/deg)@W1_l + x@W1_r + b1 ) ----
__global__ __launch_bounds__(256, 2) void sage1_kernel(
    const float* __restrict__ x,
    const float* __restrict__ Wl,
    const float* __restrict__ Wr,
    const float* __restrict__ b) {
    __shared__ float s_a[32 * FD];
    __shared__ float s_x[32 * FD];
    __shared__ float s_inv[32];
    int tid = threadIdx.x;
    int nb = blockIdx.x * 32;

    if (tid < 32) {
        int n = nb + tid;
        float d = (n < NN) ? g_deg[n] : 1.f;
        s_inv[tid] = 1.f / fmaxf(d, 1.f);
    }
    __syncthreads();
    for (int idx = tid; idx < 32 * FD; idx += 256) {
        int n = idx >> 7;
        int node = nb + n;
        float a = 0.f, xv = 0.f;
        if (node < NN) {
            int k = idx & 127;
            a = g_agg[(size_t)node * FD + k] * s_inv[n];
            xv = x[(size_t)node * FD + k];
        }
        s_a[idx] = a;
        s_x[idx] = xv;
    }
    __syncthreads();

    int ty = tid >> 5, tx = tid & 31;
    int c0 = tx * 4;         // 4 output cols per thread
    int nl = ty * 4;         // 4 nodes per thread (2 f32x2 pairs)

    u64 acc[2][4];
#pragma unroll
    for (int j = 0; j < 4; ++j) {
        float bj = __ldg(b + c0 + j);
        u64 bb = pk2(bj, bj);
        acc[0][j] = bb;
        acc[1][j] = bb;
    }

#pragma unroll 4
    for (int k = 0; k < FD; ++k) {
        float4 wl = __ldg(reinterpret_cast<const float4*>(Wl + (size_t)k * FD) + tx);
        float4 wr = __ldg(reinterpret_cast<const float4*>(Wr + (size_t)k * FD) + tx);
        u64 wlp[4] = {pk2(wl.x, wl.x), pk2(wl.y, wl.y),
                      pk2(wl.z, wl.z), pk2(wl.w, wl.w)};
        u64 wrp[4] = {pk2(wr.x, wr.x), pk2(wr.y, wr.y),
                      pk2(wr.z, wr.z), pk2(wr.w, wr.w)};
#pragma unroll
        for (int p = 0; p < 2; ++p) {
            int base = (nl + 2 * p) * FD + k;
            u64 ap = pk2(s_a[base], s_a[base + FD]);
            u64 xp = pk2(s_x[base], s_x[base + FD]);
#pragma unroll
            for (int j = 0; j < 4; ++j) {
                acc[p][j] = fma2(ap, wlp[j], acc[p][j]);
                acc[p][j] = fma2(xp, wrp[j], acc[p][j]);
            }
        }
    }

#pragma unroll
    for (int p = 0; p < 2; ++p) {
        float lo[4], hi[4];
#pragma unroll
        for (int j = 0; j < 4; ++j) unpk(acc[p][j], lo[j], hi[j]);
        int node0 = nb + nl + 2 * p;
        if (node0 < NN) {
            float4 v = make_float4(fmaxf(lo[0], 0.f), fmaxf(lo[1], 0.f),
                                   fmaxf(lo[2], 0.f), fmaxf(lo[3], 0.f));
            *reinterpret_cast<float4*>(g_h + (size_t)node0 * FD + c0) = v;
        }
        if (node0 + 1 < NN) {
            float4 v = make_float4(fmaxf(hi[0], 0.f), fmaxf(hi[1], 0.f),
                                   fmaxf(hi[2], 0.f), fmaxf(hi[3], 0.f));
            *reinterpret_cast<float4*>(g_h + (size_t)(node0 + 1) * FD + c0) = v;
        }
    }
}

// ---- layer-2 projection: p = h@W2_l, r = h@W2_r + b2  (both [N,40]) ----
__global__ __launch_bounds__(256, 2) void proj2_kernel(
    const float* __restrict__ Wl,
    const float* __restrict__ Wr,
    const float* __restrict__ b2) {
    __shared__ float sh[128 * 68];
    int tid = threadIdx.x;
    int nb = blockIdx.x * 64;

    for (int idx = tid; idx < 64 * FD; idx += 256) {
        int n = idx >> 7, k = idx & 127, nd = nb + n;
        sh[k * 68 + n] = (nd < NN) ? g_h[(size_t)nd * FD + k] : 0.f;
    }
    __syncthreads();

    int ty = tid >> 5, tx = tid & 31;
    bool act = tx < 20;
    int cx = act ? tx : 19;
    int c0 = 2 * cx;
    int nl = ty * 8;

    u64 accP[4][2], accR[4][2];
    {
        float b0 = __ldg(b2 + c0), b1v = __ldg(b2 + c0 + 1);
        u64 z = pk2(0.f, 0.f), bb0 = pk2(b0, b0), bb1 = pk2(b1v, b1v);
#pragma unroll
        for (int p = 0; p < 4; ++p) {
            accP[p][0] = z; accP[p][1] = z;
            accR[p][0] = bb0; accR[p][1] = bb1;
        }
    }

#pragma unroll 4
    for (int k = 0; k < FD; ++k) {
        float2 wl = *reinterpret_cast<const float2*>(Wl + (size_t)k * NC + c0);
        float2 wr = *reinterpret_cast<const float2*>(Wr + (size_t)k * NC + c0);
        u64 wl0 = pk2(wl.x, wl.x), wl1 = pk2(wl.y, wl.y);
        u64 wr0 = pk2(wr.x, wr.x), wr1 = pk2(wr.y, wr.y);
        ulonglong2 h01 = *reinterpret_cast<const ulonglong2*>(sh + k * 68 + nl);
        ulonglong2 h23 = *reinterpret_cast<const ulonglong2*>(sh + k * 68 + nl + 4);

        accP[0][0] = fma2(h01.x, wl0, accP[0][0]);
        accP[0][1] = fma2(h01.x, wl1, accP[0][1]);
        accP[1][0] = fma2(h01.y, wl0, accP[1][0]);
        accP[1][1] = fma2(h01.y, wl1, accP[1][1]);
        accP[2][0] = fma2(h23.x, wl0, accP[2][0]);
        accP[2][1] = fma2(h23.x, wl1, accP[2][1]);
        accP[3][0] = fma2(h23.y, wl0, accP[3][0]);
        accP[3][1] = fma2(h23.y, wl1, accP[3][1]);
        accR[0][0] = fma2(h01.x, wr0, accR[0][0]);
        accR[0][1] = fma2(h01.x, wr1, accR[0][1]);
        accR[1][0] = fma2(h01.y, wr0, accR[1][0]);
        accR[1][1] = fma2(h01.y, wr1, accR[1][1]);
        accR[2][0] = fma2(h23.x, wr0, accR[2][0]);
        accR[2][1] = fma2(h23.x, wr1, accR[2][1]);
        accR[3][0] = fma2(h23.y, wr0, accR[3][0]);
        accR[3][1] = fma2(h23.y, wr1, accR[3][1]);
    }

    if (act) {
#pragma unroll
        for (int p = 0; p < 4; ++p) {
            int n0 = nb + nl + 2 * p;
            float pa0, pa1, pb0, pb1, ra0, ra1, rb0, rb1;
            unpk(accP[p][0], pa0, pa1);
            unpk(accP[p][1], pb0, pb1);
            unpk(accR[p][0], ra0, ra1);
            unpk(accR[p][1], rb0, rb1);
            if (n0 < NN) {
                *reinterpret_cast<float2*>(g_p + (size_t)n0 * NC + c0) = make_float2(pa0, pb0);
                *reinterpret_cast<float2*>(g_r + (size_t)n0 * NC + c0) = make_float2(ra0, rb0);
            }
            if (n0 + 1 < NN) {
                *reinterpret_cast<float2*>(g_p + (size_t)(n0 + 1) * NC + c0) = make_float2(pa1, pb1);
                *reinterpret_cast<float2*>(g_r + (size_t)(n0 + 1) * NC + c0) = make_float2(ra1, rb1);
            }
        }
    }
}

// ---- final: out = log_softmax(relu(agg2/deg + r)), one warp per node ----
__global__ void final_kernel(float* __restrict__ out) {
    int lane = threadIdx.x & 31;
    int node = blockIdx.x * 8 + (threadIdx.x >> 5);  // 6250*8 = 50000 exactly
    bool act = lane < 20;
    int cx = act ? lane : 19;

    float inv = 1.f / fmaxf(g_deg[node], 1.f);
    float2 a = *reinterpret_cast<const float2*>(g_agg + (size_t)node * NC + 2 * cx);
    float2 r = *reinterpret_cast<const float2*>(g_r + (size_t)node * NC + 2 * cx);
    float za = fmaxf(fmaf(a.x, inv, r.x), 0.f);
    float zb = fmaxf(fmaf(a.y, inv, r.y), 0.f);

    float m = act ? fmaxf(za, zb) : -3.0e38f;
#pragma unroll
    for (int o = 16; o > 0; o >>= 1)
        m = fmaxf(m, __shfl_xor_sync(0xffffffffu, m, o));
    float s = act ? (expf(za - m) + expf(zb - m)) : 0.f;
#pragma unroll
    for (int o = 16; o > 0; o >>= 1)
        s += __shfl_xor_sync(0xffffffffu, s, o);
    float lse = m + logf(s);

    if (act)
        *reinterpret_cast<float2*>(out + (size_t)node * NC + 2 * lane) =
            make_float2(za - lse, zb - lse);
}

extern "C" void kernel_launch(void* const* d_in, const int* in_sizes, int n_in,
                              void* d_out, int out_size) {
    const float* x   = (const float*)d_in[0];
    const int*   ei  = (const int*)d_in[1];
    const float* W1l = (const float*)d_in[2];
    const float* W1r = (const float*)d_in[3];
    const float* b1  = (const float*)d_in[4];
    const float* W2l = (const float*)d_in[5];
    const float* W2r = (const float*)d_in[6];
    const float* b2  = (const float*)d_in[7];
    float* out = (float*)d_out;

    zero1_kernel<<<6250, 256>>>();
    scatter1_kernel<<<1184, 256>>>(x, ei);       // R2-proven resident grid
    sage1_kernel<<<1563, 256>>>(x, W1l, W1r, b1);
    zero2_kernel<<<1954, 256>>>();
    proj2_kernel<<<782, 256>>>(W2l, W2r, b2);    // 64 nodes/block
    scatter2_kernel<<<1184, 256>>>(ei);          // resident grid, 3 edges/warp
    final_kernel<<<6250, 256>>>(out);
}

// round 8
// speedup vs baseline: 1.6584x; 1.2311x over previous
#include <cuda_runtime.h>
#include <math.h>

#define NN 50000
#define NE 800000
#define FD 128
#define NC 40
#define NB_SCAN 196   // ceil(50000/256)

typedef unsigned long long u64;

// Scratch (device globals: allocation-free per harness rules)
__device__ __align__(16) float g_agg[(size_t)NN * FD];  // layer1 mean [NN,128]; reused [NN,40] layer2
__device__ __align__(16) float g_h[(size_t)NN * FD];
__device__ __align__(16) float g_p[(size_t)NN * NC];    // h @ W2_l
__device__ __align__(16) float g_r[(size_t)NN * NC];    // h @ W2_r + b2
__device__ int g_cnt[NN];
__device__ int g_start[NN + 1];
__device__ int g_cursor[NN];
__device__ int g_srcs[NE];
__device__ int g_bsum[NB_SCAN];

// ---- packed f32x2 helpers (Blackwell dual-fp32 pipe) ----
__device__ __forceinline__ u64 pk2(float lo, float hi) {
    u64 r; asm("mov.b64 %0, {%1, %2};" : "=l"(r) : "f"(lo), "f"(hi)); return r;
}
__device__ __forceinline__ u64 fma2(u64 a, u64 b, u64 c) {
    u64 d; asm("fma.rn.f32x2 %0, %1, %2, %3;" : "=l"(d) : "l"(a), "l"(b), "l"(c)); return d;
}
__device__ __forceinline__ void unpk(u64 v, float& lo, float& hi) {
    asm("mov.b64 {%0, %1}, %2;" : "=f"(lo), "=f"(hi) : "l"(v));
}

// ================= CSR build =================
__global__ void zero_cnt_kernel() {
    int i = blockIdx.x * blockDim.x + threadIdx.x;
    if (i < NN) { g_cnt[i] = 0; g_cursor[i] = 0; }
}

__global__ void hist_kernel(const int* __restrict__ ei) {
    int e = blockIdx.x * blockDim.x + threadIdx.x;   // 3125*256 = 800000 exact
    int dst = __ldg(ei + NE + e);
    atomicAdd(&g_cnt[dst], 1);
}

__global__ void scanA_kernel() {
    __shared__ int sm[256];
    int i = blockIdx.x * 256 + threadIdx.x;
    int v = (i < NN) ? g_cnt[i] : 0;
    sm[threadIdx.x] = v;
    __syncthreads();
#pragma unroll
    for (int off = 1; off < 256; off <<= 1) {
        int t = (threadIdx.x >= off) ? sm[threadIdx.x - off] : 0;
        __syncthreads();
        sm[threadIdx.x] += t;
        __syncthreads();
    }
    if (i < NN) g_start[i] = sm[threadIdx.x] - v;   // block-local exclusive
    if (threadIdx.x == 255) g_bsum[blockIdx.x] = sm[255];
}

__global__ void scanB_kernel() {
    __shared__ int sm[256];
    int t = threadIdx.x;
    int v = (t < NB_SCAN) ? g_bsum[t] : 0;
    sm[t] = v;
    __syncthreads();
#pragma unroll
    for (int off = 1; off < 256; off <<= 1) {
        int u = (t >= off) ? sm[t - off] : 0;
        __syncthreads();
        sm[t] += u;
        __syncthreads();
    }
    if (t < NB_SCAN) g_bsum[t] = sm[t] - v;         // exclusive block offsets
}

__global__ void scanC_kernel() {
    int i = blockIdx.x * 256 + threadIdx.x;
    if (i < NN) g_start[i] += g_bsum[blockIdx.x];
    if (i == 0) g_start[NN] = NE;
}

__global__ void fill_kernel(const int* __restrict__ ei) {
    int e = blockIdx.x * blockDim.x + threadIdx.x;   // exact 800000
    int src = __ldg(ei + e);
    int dst = __ldg(ei + NE + e);
    int pos = g_start[dst] + atomicAdd(&g_cursor[dst], 1);
    g_srcs[pos] = src;
}

// ================= layer-1 mean aggregation: one warp per node =================
__global__ void agg1_kernel(const float* __restrict__ x) {
    int lane = threadIdx.x & 31;
    int node = blockIdx.x * 8 + (threadIdx.x >> 5);  // 6250*8 = 50000 exact
    int s0 = g_start[node], s1 = g_start[node + 1];
    float4 acc = make_float4(0.f, 0.f, 0.f, 0.f);
    int j = s0;
    for (; j + 1 < s1; j += 2) {
        int sa = __ldg(g_srcs + j);
        int sb = __ldg(g_srcs + j + 1);
        float4 va = __ldg(reinterpret_cast<const float4*>(x) + (size_t)sa * 32 + lane);
        float4 vb = __ldg(reinterpret_cast<const float4*>(x) + (size_t)sb * 32 + lane);
        acc.x += va.x + vb.x; acc.y += va.y + vb.y;
        acc.z += va.z + vb.z; acc.w += va.w + vb.w;
    }
    if (j < s1) {
        int sa = __ldg(g_srcs + j);
        float4 va = __ldg(reinterpret_cast<const float4*>(x) + (size_t)sa * 32 + lane);
        acc.x += va.x; acc.y += va.y; acc.z += va.z; acc.w += va.w;
    }
    float inv = 1.f / fmaxf((float)(s1 - s0), 1.f);
    acc.x *= inv; acc.y *= inv; acc.z *= inv; acc.w *= inv;
    *reinterpret_cast<float4*>(g_agg + (size_t)node * FD + lane * 4) = acc;
}

// ================= layer-2 mean aggregation: 3 nodes/warp, 10 lanes each ========
__global__ void agg2_kernel() {
    int lane = threadIdx.x & 31;
    int w = blockIdx.x * 8 + (threadIdx.x >> 5);
    if (lane >= 30) return;
    int g = (lane >= 20) ? 2 : ((lane >= 10) ? 1 : 0);
    int c = lane - 10 * g;
    int node = w * 3 + g;
    if (node >= NN) return;
    int s0 = g_start[node], s1 = g_start[node + 1];
    float4 acc = make_float4(0.f, 0.f, 0.f, 0.f);
    for (int j = s0; j < s1; ++j) {
        int s = __ldg(g_srcs + j);
        float4 v = __ldg(reinterpret_cast<const float4*>(g_p) + (size_t)s * 10 + c);
        acc.x += v.x; acc.y += v.y; acc.z += v.z; acc.w += v.w;
    }
    float inv = 1.f / fmaxf((float)(s1 - s0), 1.f);
    acc.x *= inv; acc.y *= inv; acc.z *= inv; acc.w *= inv;
    *reinterpret_cast<float4*>(g_agg + (size_t)node * NC + c * 4) = acc;
}

// ---- layer 1 GEMM (R2-proven): h = relu( agg@W1_l + x@W1_r + b1 ) ----
__global__ __launch_bounds__(256, 2) void sage1_kernel(
    const float* __restrict__ x,
    const float* __restrict__ Wl,
    const float* __restrict__ Wr,
    const float* __restrict__ b) {
    __shared__ float s_a[32 * FD];
    __shared__ float s_x[32 * FD];
    int tid = threadIdx.x;
    int nb = blockIdx.x * 32;

    for (int idx = tid; idx < 32 * FD; idx += 256) {
        int n = idx >> 7;
        int node = nb + n;
        float a = 0.f, xv = 0.f;
        if (node < NN) {
            int k = idx & 127;
            a = g_agg[(size_t)node * FD + k];
            xv = x[(size_t)node * FD + k];
        }
        s_a[idx] = a;
        s_x[idx] = xv;
    }
    __syncthreads();

    int ty = tid >> 5, tx = tid & 31;
    int c0 = tx * 4;
    int nl = ty * 4;

    u64 acc[2][4];
#pragma unroll
    for (int j = 0; j < 4; ++j) {
        float bj = __ldg(b + c0 + j);
        u64 bb = pk2(bj, bj);
        acc[0][j] = bb;
        acc[1][j] = bb;
    }

#pragma unroll 4
    for (int k = 0; k < FD; ++k) {
        float4 wl = __ldg(reinterpret_cast<const float4*>(Wl + (size_t)k * FD) + tx);
        float4 wr = __ldg(reinterpret_cast<const float4*>(Wr + (size_t)k * FD) + tx);
        u64 wlp[4] = {pk2(wl.x, wl.x), pk2(wl.y, wl.y),
                      pk2(wl.z, wl.z), pk2(wl.w, wl.w)};
        u64 wrp[4] = {pk2(wr.x, wr.x), pk2(wr.y, wr.y),
                      pk2(wr.z, wr.z), pk2(wr.w, wr.w)};
#pragma unroll
        for (int p = 0; p < 2; ++p) {
            int base = (nl + 2 * p) * FD + k;
            u64 ap = pk2(s_a[base], s_a[base + FD]);
            u64 xp = pk2(s_x[base], s_x[base + FD]);
#pragma unroll
            for (int j = 0; j < 4; ++j) {
                acc[p][j] = fma2(ap, wlp[j], acc[p][j]);
                acc[p][j] = fma2(xp, wrp[j], acc[p][j]);
            }
        }
    }

#pragma unroll
    for (int p = 0; p < 2; ++p) {
        float lo[4], hi[4];
#pragma unroll
        for (int j = 0; j < 4; ++j) unpk(acc[p][j], lo[j], hi[j]);
        int node0 = nb + nl + 2 * p;
        if (node0 < NN) {
            float4 v = make_float4(fmaxf(lo[0], 0.f), fmaxf(lo[1], 0.f),
                                   fmaxf(lo[2], 0.f), fmaxf(lo[3], 0.f));
            *reinterpret_cast<float4*>(g_h + (size_t)node0 * FD + c0) = v;
        }
        if (node0 + 1 < NN) {
            float4 v = make_float4(fmaxf(hi[0], 0.f), fmaxf(hi[1], 0.f),
                                   fmaxf(hi[2], 0.f), fmaxf(hi[3], 0.f));
            *reinterpret_cast<float4*>(g_h + (size_t)(node0 + 1) * FD + c0) = v;
        }
    }
}

// ---- layer-2 projection: p = h@W2_l, r = h@W2_r + b2  (both [N,40]) ----
__global__ __launch_bounds__(256, 2) void proj2_kernel(
    const float* __restrict__ Wl,
    const float* __restrict__ Wr,
    const float* __restrict__ b2) {
    __shared__ float sh[128 * 68];
    int tid = threadIdx.x;
    int nb = blockIdx.x * 64;

    for (int idx = tid; idx < 64 * FD; idx += 256) {
        int n = idx >> 7, k = idx & 127, nd = nb + n;
        sh[k * 68 + n] = (nd < NN) ? g_h[(size_t)nd * FD + k] : 0.f;
    }
    __syncthreads();

    int ty = tid >> 5, tx = tid & 31;
    bool act = tx < 20;
    int cx = act ? tx : 19;
    int c0 = 2 * cx;
    int nl = ty * 8;

    u64 accP[4][2], accR[4][2];
    {
        float b0 = __ldg(b2 + c0), b1v = __ldg(b2 + c0 + 1);
        u64 z = pk2(0.f, 0.f), bb0 = pk2(b0, b0), bb1 = pk2(b1v, b1v);
#pragma unroll
        for (int p = 0; p < 4; ++p) {
            accP[p][0] = z; accP[p][1] = z;
            accR[p][0] = bb0; accR[p][1] = bb1;
        }
    }

#pragma unroll 4
    for (int k = 0; k < FD; ++k) {
        float2 wl = *reinterpret_cast<const float2*>(Wl + (size_t)k * NC + c0);
        float2 wr = *reinterpret_cast<const float2*>(Wr + (size_t)k * NC + c0);
        u64 wl0 = pk2(wl.x, wl.x), wl1 = pk2(wl.y, wl.y);
        u64 wr0 = pk2(wr.x, wr.x), wr1 = pk2(wr.y, wr.y);
        ulonglong2 h01 = *reinterpret_cast<const ulonglong2*>(sh + k * 68 + nl);
        ulonglong2 h23 = *reinterpret_cast<const ulonglong2*>(sh + k * 68 + nl + 4);

        accP[0][0] = fma2(h01.x, wl0, accP[0][0]);
        accP[0][1] = fma2(h01.x, wl1, accP[0][1]);
        accP[1][0] = fma2(h01.y, wl0, accP[1][0]);
        accP[1][1] = fma2(h01.y, wl1, accP[1][1]);
        accP[2][0] = fma2(h23.x, wl0, accP[2][0]);
        accP[2][1] = fma2(h23.x, wl1, accP[2][1]);
        accP[3][0] = fma2(h23.y, wl0, accP[3][0]);
        accP[3][1] = fma2(h23.y, wl1, accP[3][1]);
        accR[0][0] = fma2(h01.x, wr0, accR[0][0]);
        accR[0][1] = fma2(h01.x, wr1, accR[0][1]);
        accR[1][0] = fma2(h01.y, wr0, accR[1][0]);
        accR[1][1] = fma2(h01.y, wr1, accR[1][1]);
        accR[2][0] = fma2(h23.x, wr0, accR[2][0]);
        accR[2][1] = fma2(h23.x, wr1, accR[2][1]);
        accR[3][0] = fma2(h23.y, wr0, accR[3][0]);
        accR[3][1] = fma2(h23.y, wr1, accR[3][1]);
    }

    if (act) {
#pragma unroll
        for (int p = 0; p < 4; ++p) {
            int n0 = nb + nl + 2 * p;
            float pa0, pa1, pb0, pb1, ra0, ra1, rb0, rb1;
            unpk(accP[p][0], pa0, pa1);
            unpk(accP[p][1], pb0, pb1);
            unpk(accR[p][0], ra0, ra1);
            unpk(accR[p][1], rb0, rb1);
            if (n0 < NN) {
                *reinterpret_cast<float2*>(g_p + (size_t)n0 * NC + c0) = make_float2(pa0, pb0);
                *reinterpret_cast<float2*>(g_r + (size_t)n0 * NC + c0) = make_float2(ra0, rb0);
            }
            if (n0 + 1 < NN) {
                *reinterpret_cast<float2*>(g_p + (size_t)(n0 + 1) * NC + c0) = make_float2(pa1, pb1);
                *reinterpret_cast<float2*>(g_r + (size_t)(n0 + 1) * NC + c0) = make_float2(ra1, rb1);
            }
        }
    }
}

// ---- final: out = log_softmax(relu(mean2 + r)), one warp per node ----
__global__ void final_kernel(float* __restrict__ out) {
    int lane = threadIdx.x & 31;
    int node = blockIdx.x * 8 + (threadIdx.x >> 5);  // 6250*8 = 50000 exact
    bool act = lane < 20;
    int cx = act ? lane : 19;

    float2 a = *reinterpret_cast<const float2*>(g_agg + (size_t)node * NC + 2 * cx);
    float2 r = *reinterpret_cast<const float2*>(g_r + (size_t)node * NC + 2 * cx);
    float za = fmaxf(a.x + r.x, 0.f);
    float zb = fmaxf(a.y + r.y, 0.f);

    float m = act ? fmaxf(za, zb) : -3.0e38f;
#pragma unroll
    for (int o = 16; o > 0; o >>= 1)
        m = fmaxf(m, __shfl_xor_sync(0xffffffffu, m, o));
    float s = act ? (expf(za - m) + expf(zb - m)) : 0.f;
#pragma unroll
    for (int o = 16; o > 0; o >>= 1)
        s += __shfl_xor_sync(0xffffffffu, s, o);
    float lse = m + logf(s);

    if (act)
        *reinterpret_cast<float2*>(out + (size_t)node * NC + 2 * lane) =
            make_float2(za - lse, zb - lse);
}

extern "C" void kernel_launch(void* const* d_in, const int* in_sizes, int n_in,
                              void* d_out, int out_size) {
    const float* x   = (const float*)d_in[0];
    const int*   ei  = (const int*)d_in[1];
    const float* W1l = (const float*)d_in[2];
    const float* W1r = (const float*)d_in[3];
    const float* b1  = (const float*)d_in[4];
    const float* W2l = (const float*)d_in[5];
    const float* W2r = (const float*)d_in[6];
    const float* b2  = (const float*)d_in[7];
    float* out = (float*)d_out;

    // CSR build (dst-sorted edge lists)
    zero_cnt_kernel<<<NB_SCAN, 256>>>();
    hist_kernel<<<3125, 256>>>(ei);          // 1 thread/edge exact
    scanA_kernel<<<NB_SCAN, 256>>>();
    scanB_kernel<<<1, 256>>>();
    scanC_kernel<<<NB_SCAN, 256>>>();
    fill_kernel<<<3125, 256>>>(ei);

    // layer 1
    agg1_kernel<<<6250, 256>>>(x);           // gather + mean, 1 warp/node
    sage1_kernel<<<1563, 256>>>(x, W1l, W1r, b1);

    // layer 2 (project first, aggregate 40-dim)
    proj2_kernel<<<782, 256>>>(W2l, W2r, b2);
    agg2_kernel<<<2084, 256>>>();            // gather + mean, 3 nodes/warp
    final_kernel<<<6250, 256>>>(out);
}

// round 9
// speedup vs baseline: 1.7739x; 1.0697x over previous
#include <cuda_runtime.h>
#include <math.h>

#define NN 50000
#define NE 800000
#define FD 128
#define NC 40
#define NB_SCAN 196   // ceil(50000/256)

typedef unsigned long long u64;

// Scratch (device globals: allocation-free per harness rules)
__device__ __align__(16) float g_agg2[(size_t)NN * NC];  // layer2 mean [NN,40]
__device__ __align__(16) float g_p[(size_t)NN * NC];     // h @ W2_l
__device__ __align__(16) float g_r[(size_t)NN * NC];     // h @ W2_r + b2
__device__ int g_cnt[NN];
__device__ int g_start[NN + 1];
__device__ int g_cursor[NN];
__device__ int g_srcs[NE];
__device__ int g_bsum[NB_SCAN];

// ---- packed f32x2 helpers (Blackwell dual-fp32 pipe) ----
__device__ __forceinline__ u64 pk2(float lo, float hi) {
    u64 r; asm("mov.b64 %0, {%1, %2};" : "=l"(r) : "f"(lo), "f"(hi)); return r;
}
__device__ __forceinline__ u64 fma2(u64 a, u64 b, u64 c) {
    u64 d; asm("fma.rn.f32x2 %0, %1, %2, %3;" : "=l"(d) : "l"(a), "l"(b), "l"(c)); return d;
}
__device__ __forceinline__ void unpk(u64 v, float& lo, float& hi) {
    asm("mov.b64 {%0, %1}, %2;" : "=f"(lo), "=f"(hi) : "l"(v));
}

// ================= CSR build =================
__global__ void zero_cnt_kernel() {
    int i = blockIdx.x * blockDim.x + threadIdx.x;
    if (i < NN) g_cnt[i] = 0;
}

__global__ void hist_kernel(const int* __restrict__ ei) {
    int e = blockIdx.x * blockDim.x + threadIdx.x;   // 3125*256 = 800000 exact
    int dst = __ldg(ei + NE + e);
    atomicAdd(&g_cnt[dst], 1);
}

__global__ void scanA_kernel() {
    __shared__ int sm[256];
    int i = blockIdx.x * 256 + threadIdx.x;
    int v = (i < NN) ? g_cnt[i] : 0;
    sm[threadIdx.x] = v;
    __syncthreads();
#pragma unroll
    for (int off = 1; off < 256; off <<= 1) {
        int t = (threadIdx.x >= off) ? sm[threadIdx.x - off] : 0;
        __syncthreads();
        sm[threadIdx.x] += t;
        __syncthreads();
    }
    if (i < NN) g_start[i] = sm[threadIdx.x] - v;   // block-local exclusive
    if (threadIdx.x == 255) g_bsum[blockIdx.x] = sm[255];
}

// scanC: add inline-computed block offset; init cursor to absolute start
__global__ void scanC_kernel() {
    int i = blockIdx.x * 256 + threadIdx.x;
    int off = 0;
    for (int j = 0; j < blockIdx.x; ++j) off += __ldg(&g_bsum[j]);
    if (i < NN) {
        int s = g_start[i] + off;
        g_start[i] = s;
        g_cursor[i] = s;
    }
    if (i == 0) g_start[NN] = NE;
}

__global__ void fill_kernel(const int* __restrict__ ei) {
    int e = blockIdx.x * blockDim.x + threadIdx.x;   // exact 800000
    int src = __ldg(ei + e);
    int dst = __ldg(ei + NE + e);
    int pos = atomicAdd(&g_cursor[dst], 1);
    g_srcs[pos] = src;
}

// ================= MEGA kernel: agg1 + sage1 GEMM + layer-2 projection ========
// 32 nodes/block, 256 threads. Dynamic SMEM: s_a[32*128], s_x[32*128],
// s_h[128*36] (k-major, padded).
__global__ __launch_bounds__(256) void mega_kernel(
    const float* __restrict__ x,
    const float* __restrict__ W1l,
    const float* __restrict__ W1r,
    const float* __restrict__ b1,
    const float* __restrict__ W2l,
    const float* __restrict__ W2r,
    const float* __restrict__ b2) {
    extern __shared__ float sm[];
    float* s_a = sm;                 // [32][128] node-major
    float* s_x = sm + 32 * FD;       // [32][128]
    float* s_h = sm + 64 * FD;       // [128][36] k-major (col-major h)

    int tid = threadIdx.x;
    int lane = tid & 31;
    int ty = tid >> 5;               // warp 0..7
    int nb = blockIdx.x * 32;

    // ---------- Phase A: aggregation (warp per node, 4 nodes per warp) ----------
#pragma unroll
    for (int i = 0; i < 4; ++i) {
        int nloc = ty * 4 + i;
        int node = nb + nloc;
        float4 acc = make_float4(0.f, 0.f, 0.f, 0.f);
        float4 xrow = make_float4(0.f, 0.f, 0.f, 0.f);
        if (node < NN) {
            int s0 = __ldg(&g_start[node]), s1 = __ldg(&g_start[node + 1]);
            int j = s0;
            for (; j + 1 < s1; j += 2) {
                int sa = __ldg(g_srcs + j);
                int sb = __ldg(g_srcs + j + 1);
                float4 va = __ldg(reinterpret_cast<const float4*>(x) + (size_t)sa * 32 + lane);
                float4 vb = __ldg(reinterpret_cast<const float4*>(x) + (size_t)sb * 32 + lane);
                acc.x += va.x + vb.x; acc.y += va.y + vb.y;
                acc.z += va.z + vb.z; acc.w += va.w + vb.w;
            }
            if (j < s1) {
                int sa = __ldg(g_srcs + j);
                float4 va = __ldg(reinterpret_cast<const float4*>(x) + (size_t)sa * 32 + lane);
                acc.x += va.x; acc.y += va.y; acc.z += va.z; acc.w += va.w;
            }
            float inv = 1.f / fmaxf((float)(s1 - s0), 1.f);
            acc.x *= inv; acc.y *= inv; acc.z *= inv; acc.w *= inv;
            xrow = __ldg(reinterpret_cast<const float4*>(x) + (size_t)node * 32 + lane);
        }
        *reinterpret_cast<float4*>(s_a + nloc * FD + lane * 4) = acc;
        *reinterpret_cast<float4*>(s_x + nloc * FD + lane * 4) = xrow;
    }
    __syncthreads();

    // ---------- Phase B: layer-1 GEMM (R7-proven inner loop) ----------
    {
        int tx = lane;
        int c0 = tx * 4;
        int nl = ty * 4;

        u64 acc[2][4];
#pragma unroll
        for (int j = 0; j < 4; ++j) {
            float bj = __ldg(b1 + c0 + j);
            u64 bb = pk2(bj, bj);
            acc[0][j] = bb;
            acc[1][j] = bb;
        }

#pragma unroll 4
        for (int k = 0; k < FD; ++k) {
            float4 wl = __ldg(reinterpret_cast<const float4*>(W1l + (size_t)k * FD) + tx);
            float4 wr = __ldg(reinterpret_cast<const float4*>(W1r + (size_t)k * FD) + tx);
            u64 wlp[4] = {pk2(wl.x, wl.x), pk2(wl.y, wl.y),
                          pk2(wl.z, wl.z), pk2(wl.w, wl.w)};
            u64 wrp[4] = {pk2(wr.x, wr.x), pk2(wr.y, wr.y),
                          pk2(wr.z, wr.z), pk2(wr.w, wr.w)};
#pragma unroll
            for (int p = 0; p < 2; ++p) {
                int base = (nl + 2 * p) * FD + k;
                u64 ap = pk2(s_a[base], s_a[base + FD]);
                u64 xp = pk2(s_x[base], s_x[base + FD]);
#pragma unroll
                for (int j = 0; j < 4; ++j) {
                    acc[p][j] = fma2(ap, wlp[j], acc[p][j]);
                    acc[p][j] = fma2(xp, wrp[j], acc[p][j]);
                }
            }
        }

        __syncthreads();   // s_a/s_x fully consumed before s_h writes? (s_h separate; sync for phase ordering safety of reads below)

        // write relu(h) into s_h k-major: s_h[col*36 + node_local]
#pragma unroll
        for (int p = 0; p < 2; ++p) {
            float lo[4], hi[4];
#pragma unroll
            for (int j = 0; j < 4; ++j) unpk(acc[p][j], lo[j], hi[j]);
            int n0 = nl + 2 * p;
#pragma unroll
            for (int j = 0; j < 4; ++j) {
                s_h[(c0 + j) * 36 + n0] = fmaxf(lo[j], 0.f);
                s_h[(c0 + j) * 36 + n0 + 1] = fmaxf(hi[j], 0.f);
            }
        }
    }
    __syncthreads();

    // ---------- Phase C: layer-2 projection p = h@W2_l, r = h@W2_r + b2 ----------
    {
        int tx = lane;
        bool act = tx < 20;
        int cx = act ? tx : 19;
        int c0 = 2 * cx;
        int nl = ty * 4;     // 4 nodes per warp

        u64 accP[2][2], accR[2][2];
        {
            float b0 = __ldg(b2 + c0), b1v = __ldg(b2 + c0 + 1);
            u64 z = pk2(0.f, 0.f), bb0 = pk2(b0, b0), bb1 = pk2(b1v, b1v);
#pragma unroll
            for (int p = 0; p < 2; ++p) {
                accP[p][0] = z; accP[p][1] = z;
                accR[p][0] = bb0; accR[p][1] = bb1;
            }
        }

#pragma unroll 4
        for (int k = 0; k < FD; ++k) {
            float2 wl = *reinterpret_cast<const float2*>(W2l + (size_t)k * NC + c0);
            float2 wr = *reinterpret_cast<const float2*>(W2r + (size_t)k * NC + c0);
            u64 wl0 = pk2(wl.x, wl.x), wl1 = pk2(wl.y, wl.y);
            u64 wr0 = pk2(wr.x, wr.x), wr1 = pk2(wr.y, wr.y);
            ulonglong2 h01 = *reinterpret_cast<const ulonglong2*>(s_h + k * 36 + nl);

            accP[0][0] = fma2(h01.x, wl0, accP[0][0]);
            accP[0][1] = fma2(h01.x, wl1, accP[0][1]);
            accP[1][0] = fma2(h01.y, wl0, accP[1][0]);
            accP[1][1] = fma2(h01.y, wl1, accP[1][1]);
            accR[0][0] = fma2(h01.x, wr0, accR[0][0]);
            accR[0][1] = fma2(h01.x, wr1, accR[0][1]);
            accR[1][0] = fma2(h01.y, wr0, accR[1][0]);
            accR[1][1] = fma2(h01.y, wr1, accR[1][1]);
        }

        if (act) {
#pragma unroll
            for (int p = 0; p < 2; ++p) {
                int n0 = nb + nl + 2 * p;
                float pa0, pa1, pb0, pb1, ra0, ra1, rb0, rb1;
                unpk(accP[p][0], pa0, pa1);
                unpk(accP[p][1], pb0, pb1);
                unpk(accR[p][0], ra0, ra1);
                unpk(accR[p][1], rb0, rb1);
                if (n0 < NN) {
                    *reinterpret_cast<float2*>(g_p + (size_t)n0 * NC + c0) = make_float2(pa0, pb0);
                    *reinterpret_cast<float2*>(g_r + (size_t)n0 * NC + c0) = make_float2(ra0, rb0);
                }
                if (n0 + 1 < NN) {
                    *reinterpret_cast<float2*>(g_p + (size_t)(n0 + 1) * NC + c0) = make_float2(pa1, pb1);
                    *reinterpret_cast<float2*>(g_r + (size_t)(n0 + 1) * NC + c0) = make_float2(ra1, rb1);
                }
            }
        }
    }
}

// ================= layer-2 mean aggregation: 3 nodes/warp, 10 lanes each ========
__global__ void agg2_kernel() {
    int lane = threadIdx.x & 31;
    int w = blockIdx.x * 8 + (threadIdx.x >> 5);
    if (lane >= 30) return;
    int g = (lane >= 20) ? 2 : ((lane >= 10) ? 1 : 0);
    int c = lane - 10 * g;
    int node = w * 3 + g;
    if (node >= NN) return;
    int s0 = g_start[node], s1 = g_start[node + 1];
    float4 acc = make_float4(0.f, 0.f, 0.f, 0.f);
    int j = s0;
    for (; j + 1 < s1; j += 2) {
        int sa = __ldg(g_srcs + j);
        int sb = __ldg(g_srcs + j + 1);
        float4 va = __ldg(reinterpret_cast<const float4*>(g_p) + (size_t)sa * 10 + c);
        float4 vb = __ldg(reinterpret_cast<const float4*>(g_p) + (size_t)sb * 10 + c);
        acc.x += va.x + vb.x; acc.y += va.y + vb.y;
        acc.z += va.z + vb.z; acc.w += va.w + vb.w;
    }
    if (j < s1) {
        int s = __ldg(g_srcs + j);
        float4 v = __ldg(reinterpret_cast<const float4*>(g_p) + (size_t)s * 10 + c);
        acc.x += v.x; acc.y += v.y; acc.z += v.z; acc.w += v.w;
    }
    float inv = 1.f / fmaxf((float)(s1 - s0), 1.f);
    acc.x *= inv; acc.y *= inv; acc.z *= inv; acc.w *= inv;
    *reinterpret_cast<float4*>(g_agg2 + (size_t)node * NC + c * 4) = acc;
}

// ---- final: out = log_softmax(relu(mean2 + r)), one warp per node ----
__global__ void final_kernel(float* __restrict__ out) {
    int lane = threadIdx.x & 31;
    int node = blockIdx.x * 8 + (threadIdx.x >> 5);  // 6250*8 = 50000 exact
    bool act = lane < 20;
    int cx = act ? lane : 19;

    float2 a = *reinterpret_cast<const float2*>(g_agg2 + (size_t)node * NC + 2 * cx);
    float2 r = *reinterpret_cast<const float2*>(g_r + (size_t)node * NC + 2 * cx);
    float za = fmaxf(a.x + r.x, 0.f);
    float zb = fmaxf(a.y + r.y, 0.f);

    float m = act ? fmaxf(za, zb) : -3.0e38f;
#pragma unroll
    for (int o = 16; o > 0; o >>= 1)
        m = fmaxf(m, __shfl_xor_sync(0xffffffffu, m, o));
    float s = act ? (expf(za - m) + expf(zb - m)) : 0.f;
#pragma unroll
    for (int o = 16; o > 0; o >>= 1)
        s += __shfl_xor_sync(0xffffffffu, s, o);
    float lse = m + logf(s);

    if (act)
        *reinterpret_cast<float2*>(out + (size_t)node * NC + 2 * lane) =
            make_float2(za - lse, zb - lse);
}

extern "C" void kernel_launch(void* const* d_in, const int* in_sizes, int n_in,
                              void* d_out, int out_size) {
    const float* x   = (const float*)d_in[0];
    const int*   ei  = (const int*)d_in[1];
    const float* W1l = (const float*)d_in[2];
    const float* W1r = (const float*)d_in[3];
    const float* b1  = (const float*)d_in[4];
    const float* W2l = (const float*)d_in[5];
    const float* W2r = (const float*)d_in[6];
    const float* b2  = (const float*)d_in[7];
    float* out = (float*)d_out;

    // dynamic smem: s_a(16KB) + s_x(16KB) + s_h(128*36*4 = 18KB) = 50KB
    static const int MEGA_SMEM = (64 * FD + 128 * 36) * 4;
    cudaFuncSetAttribute(mega_kernel, cudaFuncAttributeMaxDynamicSharedMemorySize,
                         MEGA_SMEM);

    // CSR build (dst-sorted edge lists)
    zero_cnt_kernel<<<NB_SCAN, 256>>>();
    hist_kernel<<<3125, 256>>>(ei);
    scanA_kernel<<<NB_SCAN, 256>>>();
    scanC_kernel<<<NB_SCAN, 256>>>();
    fill_kernel<<<3125, 256>>>(ei);

    // fused: agg1 + layer-1 GEMM + layer-2 projection
    mega_kernel<<<1563, 256, MEGA_SMEM>>>(x, W1l, W1r, b1, W2l, W2r, b2);

    // layer-2 aggregation over 40-dim projections + softmax
    agg2_kernel<<<2084, 256>>>();
    final_kernel<<<6250, 256>>>(out);
}